// round 6
// baseline (speedup 1.0000x reference)
#include <cuda_runtime.h>
#include <math_constants.h>

// Problem shapes (fixed by the dataset instance)
#define NVARS_MAX 2000000
#define N0_MAX    4000000
#define N1_MAX    2000000
#define N2_MAX    1000000

// Scratch: intermediates live in device globals (no allocation allowed).
__device__ float g_x [2 + 2 * NVARS_MAX];   // encoded input, 16 MB
__device__ float g_b0[N0_MAX];              // layer0 out,   16 MB
__device__ float g_b1[N1_MAX];              // layer1 out,    8 MB
__device__ float g_b2[N2_MAX];              // layer2 out,    4 MB

// ---------------------------------------------------------------------------
// Encode: x[0] = -inf, x[1] = 0, x[2+2i] = w[i], x[3+2i] = log1mexp(w[i])
// ---------------------------------------------------------------------------
__global__ void encode_kernel(const float* __restrict__ w, float* __restrict__ x, int n)
{
    int i = blockIdx.x * blockDim.x + threadIdx.x;
    if (i >= n) return;
    float p = w[i];
    float neg;
    if (p > -0.69314718056f) {
        neg = __logf(-expm1f(p));
    } else {
        neg = log1pf(-__expf(p));
    }
    reinterpret_cast<float2*>(x + 2)[i] = make_float2(p, neg);
    if (i == 0) {
        x[0] = -CUDART_INF_F;
        x[1] = 0.0f;
    }
}

// ---------------------------------------------------------------------------
// Product layer (log semiring): out[j] = sum of 4 gathered values.
// U outputs per thread, grid-strided so every ptr load / store stays
// coalesced. All pointer quads are fetched first, then ALL 4*U gathers are
// issued before any arithmetic -> ~20 outstanding loads per thread.
// ---------------------------------------------------------------------------
template<int U>
__global__ void sum_kernel(const float* __restrict__ x,
                           const int4*  __restrict__ ptrs,
                           float*       __restrict__ out, int n)
{
    const int stride = blockDim.x * gridDim.x;
    const int j0 = blockIdx.x * blockDim.x + threadIdx.x;

    int4  p[U];
    bool  act[U];
    #pragma unroll
    for (int k = 0; k < U; k++) {
        int j = j0 + k * stride;
        act[k] = (j < n);
        if (act[k]) p[k] = ptrs[j];
    }

    float va[U], vb[U], vc[U], vd[U];
    #pragma unroll
    for (int k = 0; k < U; k++) {
        if (act[k]) {
            va[k] = __ldg(x + p[k].x);
            vb[k] = __ldg(x + p[k].y);
            vc[k] = __ldg(x + p[k].z);
            vd[k] = __ldg(x + p[k].w);
        }
    }

    #pragma unroll
    for (int k = 0; k < U; k++) {
        if (act[k]) {
            out[j0 + k * stride] = (va[k] + vb[k]) + (vc[k] + vd[k]);
        }
    }
}

// ---------------------------------------------------------------------------
// Sum layer (log semiring): stable 4-way log-sum-exp + eps, U outputs/thread.
// If m == -inf, all inputs are -inf -> emit -inf (matches reference's
// nan_to_num path). __expf(-inf) == 0 covers mixed cases.
// ---------------------------------------------------------------------------
template<int U>
__global__ void lse_kernel(const float* __restrict__ x,
                           const int4*  __restrict__ ptrs,
                           float*       __restrict__ out, int n)
{
    const int stride = blockDim.x * gridDim.x;
    const int j0 = blockIdx.x * blockDim.x + threadIdx.x;

    int4  p[U];
    bool  act[U];
    #pragma unroll
    for (int k = 0; k < U; k++) {
        int j = j0 + k * stride;
        act[k] = (j < n);
        if (act[k]) p[k] = ptrs[j];
    }

    float va[U], vb[U], vc[U], vd[U];
    #pragma unroll
    for (int k = 0; k < U; k++) {
        if (act[k]) {
            va[k] = __ldg(x + p[k].x);
            vb[k] = __ldg(x + p[k].y);
            vc[k] = __ldg(x + p[k].z);
            vd[k] = __ldg(x + p[k].w);
        }
    }

    #pragma unroll
    for (int k = 0; k < U; k++) {
        if (act[k]) {
            float m = fmaxf(fmaxf(va[k], vb[k]), fmaxf(vc[k], vd[k]));
            float r;
            if (m == -CUDART_INF_F) {
                r = -CUDART_INF_F;
            } else {
                float s = __expf(va[k] - m) + __expf(vb[k] - m)
                        + __expf(vc[k] - m) + __expf(vd[k] - m) + 1e-15f;
                r = __logf(s) + m;
            }
            out[j0 + k * stride] = r;
        }
    }
}

extern "C" void kernel_launch(void* const* d_in, const int* in_sizes, int n_in,
                              void* d_out, int out_size)
{
    // metadata order (setup_inputs dict order):
    //   0:weights 1:ptrs0 2:csr0 3:n0 4:ptrs1 5:csr1 6:n1
    //   7:ptrs2 8:csr2 9:n2 10:ptrs3 11:csr3 12:n3
    // Fallback if the scalars are not passed as inputs:
    //   0:weights 1:ptrs0 2:csr0 3:ptrs1 4:csr1 5:ptrs2 6:csr2 7:ptrs3 8:csr3
    int i0, i1, i2, i3;
    if (n_in >= 13) { i0 = 1; i1 = 4; i2 = 7; i3 = 10; }
    else            { i0 = 1; i1 = 3; i2 = 5; i3 = 7;  }

    const float* w  = (const float*)d_in[0];
    const int4*  p0 = (const int4*) d_in[i0];
    const int4*  p1 = (const int4*) d_in[i1];
    const int4*  p2 = (const int4*) d_in[i2];
    const int4*  p3 = (const int4*) d_in[i3];

    int n_vars = in_sizes[0];
    int n0 = in_sizes[i0] / 4;
    int n1 = in_sizes[i1] / 4;
    int n2 = in_sizes[i2] / 4;
    int n3 = in_sizes[i3] / 4;   // == out_size

    float *x, *b0, *b1, *b2;
    cudaGetSymbolAddress((void**)&x,  g_x);
    cudaGetSymbolAddress((void**)&b0, g_b0);
    cudaGetSymbolAddress((void**)&b1, g_b1);
    cudaGetSymbolAddress((void**)&b2, g_b2);

    const int T = 256;
    const int U = 4;
    auto blocksU = [&](int n) { return (n + T * U - 1) / (T * U); };

    encode_kernel   <<<(n_vars + T - 1) / T, T>>>(w, x, n_vars);
    sum_kernel<U>   <<<blocksU(n0), T>>>(x,  p0, b0, n0);
    lse_kernel<U>   <<<blocksU(n1), T>>>(b0, p1, b1, n1);
    sum_kernel<U>   <<<blocksU(n2), T>>>(b1, p2, b2, n2);
    lse_kernel<U>   <<<blocksU(n3), T>>>(b2, p3, (float*)d_out, n3);
}

// round 7
// speedup vs baseline: 1.1030x; 1.1030x over previous
#include <cuda_runtime.h>
#include <math_constants.h>

// Problem shapes (fixed by the dataset instance)
#define NVARS_MAX 2000000
#define N0_MAX    4000000
#define N1_MAX    2000000
#define N2_MAX    1000000

// Scratch: intermediates live in device globals (no allocation allowed).
__device__ float g_x [2 + 2 * NVARS_MAX];   // encoded input, 16 MB
__device__ float g_b0[N0_MAX];              // layer0 out,   16 MB
__device__ float g_b1[N1_MAX];              // layer1 out,    8 MB
__device__ float g_b2[N2_MAX];              // layer2 out,    4 MB

#define NBLK 592           // 148 SMs x 4 resident blocks (256 thr, <=48 regs)
#define NTHR 256

// ---------------------------------------------------------------------------
// Encode: x[0] = -inf, x[1] = 0, x[2+2i] = w[i], x[3+2i] = log1mexp(w[i])
// ---------------------------------------------------------------------------
__global__ void encode_kernel(const float* __restrict__ w, float* __restrict__ x, int n)
{
    int i = blockIdx.x * blockDim.x + threadIdx.x;
    if (i >= n) return;
    float p = w[i];
    float neg;
    if (p > -0.69314718056f) {
        neg = __logf(-expm1f(p));
    } else {
        neg = log1pf(-__expf(p));
    }
    reinterpret_cast<float2*>(x + 2)[i] = make_float2(p, neg);
    if (i == 0) {
        x[0] = -CUDART_INF_F;
        x[1] = 0.0f;
    }
}

// ---------------------------------------------------------------------------
// Product layer (log semiring): out[j] = sum of 4 gathered log-values.
// Persistent grid-stride loop; each outer iteration batches U independent
// outputs: all ptr quads fetched, then all 4*U gathers issued, then stores.
// Outer-loop software pipelining keeps the LSU continuously fed.
// ---------------------------------------------------------------------------
template<int U>
__global__ void __launch_bounds__(NTHR, 4)
sum_kernel(const float* __restrict__ x,
           const int4*  __restrict__ ptrs,
           float*       __restrict__ out, int n)
{
    const int S    = gridDim.x * blockDim.x;     // slot stride
    const int tid0 = blockIdx.x * blockDim.x + threadIdx.x;

    for (int base = tid0; base < n; base += U * S) {
        int4 p[U];
        #pragma unroll
        for (int k = 0; k < U; k++) {
            int j = base + k * S;
            if (j < n) p[k] = ptrs[j];
        }
        float va[U], vb[U], vc[U], vd[U];
        #pragma unroll
        for (int k = 0; k < U; k++) {
            int j = base + k * S;
            if (j < n) {
                va[k] = __ldg(x + p[k].x);
                vb[k] = __ldg(x + p[k].y);
                vc[k] = __ldg(x + p[k].z);
                vd[k] = __ldg(x + p[k].w);
            }
        }
        #pragma unroll
        for (int k = 0; k < U; k++) {
            int j = base + k * S;
            if (j < n) out[j] = (va[k] + vb[k]) + (vc[k] + vd[k]);
        }
    }
}

// ---------------------------------------------------------------------------
// Sum layer (log semiring): stable 4-way log-sum-exp + eps.
// m == -inf => all inputs -inf => emit -inf (matches reference nan_to_num
// path). __expf(-inf) == 0 covers mixed cases.
// ---------------------------------------------------------------------------
template<int U>
__global__ void __launch_bounds__(NTHR, 4)
lse_kernel(const float* __restrict__ x,
           const int4*  __restrict__ ptrs,
           float*       __restrict__ out, int n)
{
    const int S    = gridDim.x * blockDim.x;
    const int tid0 = blockIdx.x * blockDim.x + threadIdx.x;

    for (int base = tid0; base < n; base += U * S) {
        int4 p[U];
        #pragma unroll
        for (int k = 0; k < U; k++) {
            int j = base + k * S;
            if (j < n) p[k] = ptrs[j];
        }
        float va[U], vb[U], vc[U], vd[U];
        #pragma unroll
        for (int k = 0; k < U; k++) {
            int j = base + k * S;
            if (j < n) {
                va[k] = __ldg(x + p[k].x);
                vb[k] = __ldg(x + p[k].y);
                vc[k] = __ldg(x + p[k].z);
                vd[k] = __ldg(x + p[k].w);
            }
        }
        #pragma unroll
        for (int k = 0; k < U; k++) {
            int j = base + k * S;
            if (j < n) {
                float m = fmaxf(fmaxf(va[k], vb[k]), fmaxf(vc[k], vd[k]));
                float r;
                if (m == -CUDART_INF_F) {
                    r = -CUDART_INF_F;
                } else {
                    float s = __expf(va[k] - m) + __expf(vb[k] - m)
                            + __expf(vc[k] - m) + __expf(vd[k] - m) + 1e-15f;
                    r = __logf(s) + m;
                }
                out[j] = r;
            }
        }
    }
}

extern "C" void kernel_launch(void* const* d_in, const int* in_sizes, int n_in,
                              void* d_out, int out_size)
{
    // metadata order (setup_inputs dict order):
    //   0:weights 1:ptrs0 2:csr0 3:n0 4:ptrs1 5:csr1 6:n1
    //   7:ptrs2 8:csr2 9:n2 10:ptrs3 11:csr3 12:n3
    // Fallback if the scalars are not passed as inputs:
    //   0:weights 1:ptrs0 2:csr0 3:ptrs1 4:csr1 5:ptrs2 6:csr2 7:ptrs3 8:csr3
    int i0, i1, i2, i3;
    if (n_in >= 13) { i0 = 1; i1 = 4; i2 = 7; i3 = 10; }
    else            { i0 = 1; i1 = 3; i2 = 5; i3 = 7;  }

    const float* w  = (const float*)d_in[0];
    const int4*  p0 = (const int4*) d_in[i0];
    const int4*  p1 = (const int4*) d_in[i1];
    const int4*  p2 = (const int4*) d_in[i2];
    const int4*  p3 = (const int4*) d_in[i3];

    int n_vars = in_sizes[0];
    int n0 = in_sizes[i0] / 4;
    int n1 = in_sizes[i1] / 4;
    int n2 = in_sizes[i2] / 4;
    int n3 = in_sizes[i3] / 4;   // == out_size

    float *x, *b0, *b1, *b2;
    cudaGetSymbolAddress((void**)&x,  g_x);
    cudaGetSymbolAddress((void**)&b0, g_b0);
    cudaGetSymbolAddress((void**)&b1, g_b1);
    cudaGetSymbolAddress((void**)&b2, g_b2);

    const int U = 4;
    encode_kernel  <<<(n_vars + NTHR - 1) / NTHR, NTHR>>>(w, x, n_vars);
    sum_kernel<U>  <<<NBLK, NTHR>>>(x,  p0, b0, n0);
    lse_kernel<U>  <<<NBLK, NTHR>>>(b0, p1, b1, n1);
    sum_kernel<U>  <<<NBLK, NTHR>>>(b1, p2, b2, n2);
    lse_kernel<U>  <<<NBLK, NTHR>>>(b2, p3, (float*)d_out, n3);
}